// round 3
// baseline (speedup 1.0000x reference)
#include <cuda_runtime.h>
#include <math.h>

// Problem constants (B=8, L=2048, D=512, K=4, m=256)
#define Bn 8
#define Ln 2048
#define Dn 512
#define Mf 256
#define KLn 8192
#define ROWS_Q 16384
#define ROWS_K 65536

__device__ float g_phi_q[(size_t)ROWS_Q * Mf];   // 16 MB
__device__ float g_phi_k[(size_t)ROWS_K * Mf];   // 64 MB
__device__ float g_sq_q[ROWS_Q];
__device__ float g_sq_k[ROWS_K];
__device__ float g_Z[Bn * Mf];
__device__ float g_S[(size_t)Bn * Mf * Dn];      // 4 MB
__device__ float g_den[ROWS_Q];

__device__ __constant__ float PROJ_SCALE = 0.21022410381342864f;  // 512^-0.25
__device__ __constant__ float SQ_SCALE   = 0.022097086912079608f; // 1/(2*sqrt(512))
__device__ __constant__ float RSQ_M      = 0.0625f;               // 256^-0.5

__device__ __forceinline__ unsigned f2tf32(float x) {
    unsigned r;
    asm("cvt.rna.tf32.f32 %0, %1;" : "=r"(r) : "f"(x));
    return r;
}

// hi = tf32(x), lo = tf32(x - hi)  (x - hi is exact in fp32)
__device__ __forceinline__ void split_tf32(float x, unsigned& hi, unsigned& lo) {
    hi = f2tf32(x);
    float hif = __uint_as_float(hi);
    lo = f2tf32(x - hif);
}

__device__ __forceinline__ void mma_tf32(float c[4], const unsigned a[4], const unsigned b[2]) {
    asm volatile(
        "mma.sync.aligned.m16n8k8.row.col.f32.tf32.tf32.f32 "
        "{%0,%1,%2,%3}, {%4,%5,%6,%7}, {%8,%9}, {%0,%1,%2,%3};\n"
        : "+f"(c[0]), "+f"(c[1]), "+f"(c[2]), "+f"(c[3])
        : "r"(a[0]), "r"(a[1]), "r"(a[2]), "r"(a[3]), "r"(b[0]), "r"(b[1]));
}

// ---------------------------------------------------------------------------
// Row sum-of-squares: sq[row] = sum(x^2) / (2*sqrt(D)).  One warp per row.
// ---------------------------------------------------------------------------
__global__ void rowsumsq_kernel(const float* __restrict__ X, float* __restrict__ sq, int rows)
{
    int row  = blockIdx.x * 8 + (threadIdx.x >> 5);
    int lane = threadIdx.x & 31;
    if (row >= rows) return;
    const float4* xp = (const float4*)(X + (long)row * Dn);
    float s = 0.f;
    #pragma unroll
    for (int i = lane; i < Dn / 4; i += 32) {
        float4 v = xp[i];
        s += v.x * v.x + v.y * v.y + v.z * v.z + v.w * v.w;
    }
    #pragma unroll
    for (int o = 16; o; o >>= 1) s += __shfl_xor_sync(0xffffffffu, s, o);
    if (lane == 0) sq[row] = s * SQ_SCALE;
}

__global__ void zero_kernel(float* __restrict__ S, float* __restrict__ Z)
{
    long i = (long)blockIdx.x * 256 + threadIdx.x;
    if (i < (long)Bn * Mf * Dn) S[i] = 0.f;
    if (i < Bn * Mf)            Z[i] = 0.f;
}

// ---------------------------------------------------------------------------
// tf32x2-compensated tensor-core GEMM (3 MMAs per tile: HH + HL + LH).
//   C[M,N] = A @ B, block tile 128x64x32, 8 warps (4x2), warp tile 32x32.
//   TRANS_A=0: A is [M,K] row-major.  TRANS_A=1: A is [K,M] row-major (A^T).
//   EPI=1: phi epilogue C = exp(acc*PROJ_SCALE - sq[row]) * RSQ_M
//   EPI=2: atomicAdd into C (split-K)
//   EPI=3: fused final: fa = acc/den[row]; C=content+fa; out2=fa
// ---------------------------------------------------------------------------
#define BM 128
#define BN 64
#define BK 32
#define BKP 36
#define BNP 72

template<int TRANS_A, int EPI>
__global__ void __launch_bounds__(256)
mma_gemm(const float* __restrict__ A, const float* __restrict__ B,
         float* __restrict__ C, int Ksz, int lda, int ldb, int ldc,
         long batchA, long batchB, long batchC, int splitK,
         const float* __restrict__ sq,
         const float* __restrict__ den,
         const float* __restrict__ content,
         float* __restrict__ out2)
{
    __shared__ unsigned AsH[BM][BKP];
    __shared__ unsigned AsL[BM][BKP];
    __shared__ unsigned BsH[BK][BNP];
    __shared__ unsigned BsL[BK][BNP];

    int bz = blockIdx.z;
    int b  = bz / splitK;
    int sp = bz % splitK;
    long kBeg = (long)sp * Ksz;

    const float* Ab = A + (long)b * batchA;
    const float* Bb = B + (long)b * batchB + kBeg * ldb;
    if (TRANS_A) Ab += kBeg * lda; else Ab += kBeg;

    int rowBlk = blockIdx.y * BM;
    int colBlk = blockIdx.x * BN;
    int tid = threadIdx.x;

    // global->reg staging index maps
    int a_row = tid >> 1;            // non-trans: 128 rows x 2 threads
    int a_kb  = (tid & 1) * 16;
    int at_k  = tid >> 3;            // trans: 32 k-rows x 8 threads
    int at_mb = (tid & 7) * 16;
    int b_k   = tid >> 3;            // B: 32 k-rows x 8 threads
    int b_c   = (tid & 7) * 8;

    float4 ar[4];
    float4 br[2];

    auto ldTile = [&](long k0) {
        if (!TRANS_A) {
            const float* p = Ab + (long)(rowBlk + a_row) * lda + k0 + a_kb;
            ar[0] = *(const float4*)(p);
            ar[1] = *(const float4*)(p + 4);
            ar[2] = *(const float4*)(p + 8);
            ar[3] = *(const float4*)(p + 12);
        } else {
            const float* p = Ab + (k0 + at_k) * (long)lda + rowBlk + at_mb;
            ar[0] = *(const float4*)(p);
            ar[1] = *(const float4*)(p + 4);
            ar[2] = *(const float4*)(p + 8);
            ar[3] = *(const float4*)(p + 12);
        }
        const float* q = Bb + (k0 + b_k) * (long)ldb + colBlk + b_c;
        br[0] = *(const float4*)(q);
        br[1] = *(const float4*)(q + 4);
    };

    auto stTile = [&]() {
        float av[16] = {ar[0].x, ar[0].y, ar[0].z, ar[0].w,
                        ar[1].x, ar[1].y, ar[1].z, ar[1].w,
                        ar[2].x, ar[2].y, ar[2].z, ar[2].w,
                        ar[3].x, ar[3].y, ar[3].z, ar[3].w};
        if (!TRANS_A) {
            unsigned* dh = &AsH[a_row][a_kb];
            unsigned* dl = &AsL[a_row][a_kb];
            #pragma unroll
            for (int i = 0; i < 16; i++) split_tf32(av[i], dh[i], dl[i]);
        } else {
            #pragma unroll
            for (int i = 0; i < 16; i++) {
                unsigned h, l;
                split_tf32(av[i], h, l);
                AsH[at_mb + i][at_k] = h;
                AsL[at_mb + i][at_k] = l;
            }
        }
        float bv[8] = {br[0].x, br[0].y, br[0].z, br[0].w,
                       br[1].x, br[1].y, br[1].z, br[1].w};
        unsigned* eh = &BsH[b_k][b_c];
        unsigned* el = &BsL[b_k][b_c];
        #pragma unroll
        for (int i = 0; i < 8; i++) split_tf32(bv[i], eh[i], el[i]);
    };

    int wid = tid >> 5, lane = tid & 31;
    int gid = lane >> 2, tig = lane & 3;
    int wm = wid >> 1, wn = wid & 1;
    int wrow = wm * 32, wcol = wn * 32;

    float acc[2][4][4] = {};

    int nT = Ksz / BK;
    ldTile(0);
    for (int t = 0; t < nT; t++) {
        stTile();
        __syncthreads();
        if (t + 1 < nT) ldTile((long)(t + 1) * BK);
        #pragma unroll
        for (int kk = 0; kk < 4; kk++) {
            int kb = kk * 8;
            unsigned afh[2][4], afl[2][4], bfh[4][2], bfl[4][2];
            #pragma unroll
            for (int mi = 0; mi < 2; mi++) {
                int r = wrow + mi * 16 + gid;
                afh[mi][0] = AsH[r][kb + tig];
                afh[mi][1] = AsH[r + 8][kb + tig];
                afh[mi][2] = AsH[r][kb + tig + 4];
                afh[mi][3] = AsH[r + 8][kb + tig + 4];
                afl[mi][0] = AsL[r][kb + tig];
                afl[mi][1] = AsL[r + 8][kb + tig];
                afl[mi][2] = AsL[r][kb + tig + 4];
                afl[mi][3] = AsL[r + 8][kb + tig + 4];
            }
            #pragma unroll
            for (int ni = 0; ni < 4; ni++) {
                int c = wcol + ni * 8 + gid;
                bfh[ni][0] = BsH[kb + tig][c];
                bfh[ni][1] = BsH[kb + tig + 4][c];
                bfl[ni][0] = BsL[kb + tig][c];
                bfl[ni][1] = BsL[kb + tig + 4][c];
            }
            #pragma unroll
            for (int mi = 0; mi < 2; mi++)
                #pragma unroll
                for (int ni = 0; ni < 4; ni++) {
                    mma_tf32(acc[mi][ni], afl[mi], bfh[ni]);
                    mma_tf32(acc[mi][ni], afh[mi], bfl[ni]);
                    mma_tf32(acc[mi][ni], afh[mi], bfh[ni]);
                }
        }
        __syncthreads();
    }

    // Epilogue
    float* Cb = C + (long)b * batchC;
    #pragma unroll
    for (int mi = 0; mi < 2; mi++) {
        #pragma unroll
        for (int ni = 0; ni < 4; ni++) {
            int r0 = rowBlk + wrow + mi * 16 + gid;
            int c0 = colBlk + wcol + ni * 8 + tig * 2;
            #pragma unroll
            for (int h = 0; h < 2; h++) {
                int r = r0 + h * 8;
                float v0 = acc[mi][ni][h * 2 + 0];
                float v1 = acc[mi][ni][h * 2 + 1];
                long o = (long)r * ldc + c0;
                if (EPI == 1) {
                    float bias = sq[r];
                    Cb[o]     = expf(v0 * PROJ_SCALE - bias) * RSQ_M;
                    Cb[o + 1] = expf(v1 * PROJ_SCALE - bias) * RSQ_M;
                } else if (EPI == 2) {
                    atomicAdd(&Cb[o], v0);
                    atomicAdd(&Cb[o + 1], v1);
                } else { // EPI == 3
                    float inv = 1.0f / den[b * Ln + r];
                    float fa0 = v0 * inv, fa1 = v1 * inv;
                    long go = (long)b * batchC + o;
                    C[go]     = content[go] + fa0;
                    C[go + 1] = content[go + 1] + fa1;
                    out2[go]     = fa0;
                    out2[go + 1] = fa1;
                }
            }
        }
    }
}

// ---------------------------------------------------------------------------
// Z[b][m] = sum_k phi_k[b][k][m]
// ---------------------------------------------------------------------------
__global__ void z_kernel(const float* __restrict__ PhiK, float* __restrict__ Z)
{
    int b = blockIdx.x, chunk = blockIdx.y, m = threadIdx.x;
    const float* p = PhiK + ((long)b * KLn + (long)chunk * 256) * Mf + m;
    float s = 0.f;
    #pragma unroll 8
    for (int k = 0; k < 256; k++) s += p[(long)k * Mf];
    atomicAdd(&Z[b * Mf + m], s);
}

// ---------------------------------------------------------------------------
// den[row] = dot(phi_q[row], Z[b]) + eps.  One warp per row.
// ---------------------------------------------------------------------------
__global__ void den_kernel(const float* __restrict__ PhiQ, const float* __restrict__ Z,
                           float* __restrict__ den)
{
    int row  = blockIdx.x * 8 + (threadIdx.x >> 5);
    int lane = threadIdx.x & 31;
    int b = row / Ln;
    const float4* pq = (const float4*)(PhiQ + (long)row * Mf);
    const float4* zz = (const float4*)(Z + b * Mf);
    float s = 0.f;
    #pragma unroll
    for (int i = lane; i < Mf / 4; i += 32) {
        float4 p = pq[i], q = zz[i];
        s += p.x * q.x + p.y * q.y + p.z * q.z + p.w * q.w;
    }
    #pragma unroll
    for (int o = 16; o; o >>= 1) s += __shfl_xor_sync(0xffffffffu, s, o);
    if (lane == 0) den[row] = s + 1e-8f;
}

// ---------------------------------------------------------------------------
// Launch
// ---------------------------------------------------------------------------
#define SPLIT_S 4

extern "C" void kernel_launch(void* const* d_in, const int* in_sizes, int n_in,
                              void* d_out, int out_size)
{
    const float* content = (const float*)d_in[0];
    const float* style   = (const float*)d_in[1];
    const float* W       = (const float*)d_in[2];
    float* out = (float*)d_out;

    float *phi_q, *phi_k, *sqq, *sqk, *Z, *S, *den;
    cudaGetSymbolAddress((void**)&phi_q, g_phi_q);
    cudaGetSymbolAddress((void**)&phi_k, g_phi_k);
    cudaGetSymbolAddress((void**)&sqq,   g_sq_q);
    cudaGetSymbolAddress((void**)&sqk,   g_sq_k);
    cudaGetSymbolAddress((void**)&Z,     g_Z);
    cudaGetSymbolAddress((void**)&S,     g_S);
    cudaGetSymbolAddress((void**)&den,   g_den);

    // 1) row sum-of-squares
    rowsumsq_kernel<<<ROWS_Q / 8, 256>>>(content, sqq, ROWS_Q);
    rowsumsq_kernel<<<ROWS_K / 8, 256>>>(style, sqk, ROWS_K);

    // 2) zero S and Z
    zero_kernel<<<(Bn * Mf * Dn) / 256, 256>>>(S, Z);

    // 3) phi_q = phi(content @ W)   [16384,512]@[512,256]
    {
        dim3 g(Mf / BN, ROWS_Q / BM, 1);
        mma_gemm<0, 1><<<g, 256>>>(content, W, phi_q, Dn, Dn, Mf, Mf,
                                   0, 0, 0, 1, sqq, nullptr, nullptr, nullptr);
    }
    // 4) phi_k = phi(style @ W)     [65536,512]@[512,256]
    {
        dim3 g(Mf / BN, ROWS_K / BM, 1);
        mma_gemm<0, 1><<<g, 256>>>(style, W, phi_k, Dn, Dn, Mf, Mf,
                                   0, 0, 0, 1, sqk, nullptr, nullptr, nullptr);
    }
    // 5) Z = colsum(phi_k) per batch
    z_kernel<<<dim3(Bn, 32), 256>>>(phi_k, Z);

    // 6) S[b] = phi_k[b]^T @ style[b]  (split-K atomics)  [256,8192]^T@[8192,512]
    {
        dim3 g(Dn / BN, Mf / BM, Bn * SPLIT_S);
        mma_gemm<1, 2><<<g, 256>>>(phi_k, style, S, KLn / SPLIT_S, Mf, Dn, Dn,
                                   (long)KLn * Mf, (long)KLn * Dn, (long)Mf * Dn,
                                   SPLIT_S, nullptr, nullptr, nullptr, nullptr);
    }
    // 7) den = phi_q . Z + eps
    den_kernel<<<ROWS_Q / 8, 256>>>(phi_q, Z, den);

    // 8) num GEMM with fused final epilogue: out = content + fa, out2 = fa
    {
        dim3 g(Dn / BN, Ln / BM, Bn);
        mma_gemm<0, 3><<<g, 256>>>(phi_q, S, out, Mf, Mf, Dn, Dn,
                                   (long)Ln * Mf, (long)Mf * Dn, (long)Ln * Dn,
                                   1, nullptr, den, content, out + (long)ROWS_Q * Dn);
    }
}

// round 5
// speedup vs baseline: 1.6365x; 1.6365x over previous
#include <cuda_runtime.h>
#include <cuda_bf16.h>
#include <math.h>

// Problem constants (B=8, L=2048, D=512, K=4, m=256)
#define Bn 8
#define Ln 2048
#define Dn 512
#define Mf 256
#define KLn 8192
#define ROWS_Q 16384
#define ROWS_K 65536

__device__ float g_phi_q[(size_t)ROWS_Q * Mf];   // 16 MB
__device__ float g_phi_k[(size_t)ROWS_K * Mf];   // 64 MB
__device__ float g_sq_q[ROWS_Q];
__device__ float g_sq_k[ROWS_K];
__device__ float g_Z[Bn * Mf];
__device__ float g_S[(size_t)Bn * Mf * Dn];      // 4 MB
__device__ float g_den[ROWS_Q];

__device__ __constant__ float PROJ_SCALE = 0.21022410381342864f;  // 512^-0.25
__device__ __constant__ float SQ_SCALE   = 0.022097086912079608f; // 1/(2*sqrt(512))
__device__ __constant__ float RSQ_M      = 0.0625f;               // 256^-0.5

// pack two floats' bf16 hi parts into h, lo-residual parts into l
// (element a in low 16 bits = even k; element b in high 16 = odd k)
__device__ __forceinline__ void splitpack(float a, float b, unsigned& h, unsigned& l) {
    __nv_bfloat16 ha = __float2bfloat16_rn(a), hb = __float2bfloat16_rn(b);
    float ra = a - __bfloat162float(ha);
    float rb = b - __bfloat162float(hb);
    __nv_bfloat16 la = __float2bfloat16_rn(ra), lb = __float2bfloat16_rn(rb);
    h = (unsigned)__bfloat16_as_ushort(ha) | ((unsigned)__bfloat16_as_ushort(hb) << 16);
    l = (unsigned)__bfloat16_as_ushort(la) | ((unsigned)__bfloat16_as_ushort(lb) << 16);
}

__device__ __forceinline__ void mma_bf16(float c[4], const unsigned a[4], const unsigned b[2]) {
    asm volatile(
        "mma.sync.aligned.m16n8k16.row.col.f32.bf16.bf16.f32 "
        "{%0,%1,%2,%3}, {%4,%5,%6,%7}, {%8,%9}, {%0,%1,%2,%3};\n"
        : "+f"(c[0]), "+f"(c[1]), "+f"(c[2]), "+f"(c[3])
        : "r"(a[0]), "r"(a[1]), "r"(a[2]), "r"(a[3]), "r"(b[0]), "r"(b[1]));
}

// ---------------------------------------------------------------------------
// Row sum-of-squares: sq[row] = sum(x^2) / (2*sqrt(D)).  One warp per row.
// ---------------------------------------------------------------------------
__global__ void rowsumsq_kernel(const float* __restrict__ X, float* __restrict__ sq, int rows)
{
    int row  = blockIdx.x * 8 + (threadIdx.x >> 5);
    int lane = threadIdx.x & 31;
    if (row >= rows) return;
    const float4* xp = (const float4*)(X + (long)row * Dn);
    float s = 0.f;
    #pragma unroll
    for (int i = lane; i < Dn / 4; i += 32) {
        float4 v = xp[i];
        s += v.x * v.x + v.y * v.y + v.z * v.z + v.w * v.w;
    }
    #pragma unroll
    for (int o = 16; o; o >>= 1) s += __shfl_xor_sync(0xffffffffu, s, o);
    if (lane == 0) sq[row] = s * SQ_SCALE;
}

__global__ void zero_kernel(float* __restrict__ S, float* __restrict__ Z)
{
    long i = (long)blockIdx.x * 256 + threadIdx.x;
    if (i < (long)Bn * Mf * Dn) S[i] = 0.f;
    if (i < Bn * Mf)            Z[i] = 0.f;
}

// ---------------------------------------------------------------------------
// bf16x2-compensated tensor-core GEMM (3 MMAs per k16 slice: LH + HL + HH).
//   C[M,N] = A @ B, block tile 128x64x32, 8 warps (4x2), warp tile 32x32.
//   Operands staged in SMEM as packed bf16 pairs (u32 = 2 consecutive k).
//   TRANS_A=0: A is [M,K] row-major.  TRANS_A=1: A is [K,M] row-major (A^T).
//   EPI=1: phi epilogue C = exp(acc*PROJ_SCALE - sq[row]) * RSQ_M
//   EPI=2: atomicAdd into C (split-K)
//   EPI=3: fused final: fa = acc/den[row]; C=content+fa; out2=fa
// ---------------------------------------------------------------------------
#define BM 128
#define BN 64
#define BK 32
#define AKP 18   // packed row stride for As (16 + 2 pad)
#define BNP 68   // row stride for Bs (64 + 4 pad)

template<int TRANS_A, int EPI>
__global__ void __launch_bounds__(256, 2)
mma_gemm(const float* __restrict__ A, const float* __restrict__ B,
         float* __restrict__ C, int Ksz, int lda, int ldb, int ldc,
         long batchA, long batchB, long batchC, int splitK,
         const float* __restrict__ sq,
         const float* __restrict__ den,
         const float* __restrict__ content,
         float* __restrict__ out2)
{
    __shared__ unsigned AsH[BM][AKP];
    __shared__ unsigned AsL[BM][AKP];
    __shared__ unsigned BsH[BK / 2][BNP];
    __shared__ unsigned BsL[BK / 2][BNP];

    int bz = blockIdx.z;
    int b  = bz / splitK;
    int sp = bz % splitK;
    long kBeg = (long)sp * Ksz;

    const float* Ab = A + (long)b * batchA;
    const float* Bb = B + (long)b * batchB + kBeg * ldb;
    if (TRANS_A) Ab += kBeg * lda; else Ab += kBeg;

    int rowBlk = blockIdx.y * BM;
    int colBlk = blockIdx.x * BN;
    int tid = threadIdx.x;

    // staging index maps
    int a_row = tid >> 1;            // non-trans A: 128 rows x 2 threads
    int a_kb  = (tid & 1) * 16;      // 16 floats each
    int at_kp = tid >> 4;            // trans A: k-pair 0..15
    int at_m0 = (tid & 15) * 8;      // 8 m-columns each
    int b_kp  = tid >> 4;            // B: k-pair 0..15
    int b_c   = (tid & 15) * 4;      // 4 columns each

    float4 ar[4];
    float4 br[2];

    auto ldTile = [&](long k0) {
        if (!TRANS_A) {
            const float* p = Ab + (long)(rowBlk + a_row) * lda + k0 + a_kb;
            ar[0] = *(const float4*)(p);
            ar[1] = *(const float4*)(p + 4);
            ar[2] = *(const float4*)(p + 8);
            ar[3] = *(const float4*)(p + 12);
        } else {
            const float* p0 = Ab + (k0 + 2 * at_kp) * (long)lda + rowBlk + at_m0;
            const float* p1 = p0 + lda;
            ar[0] = *(const float4*)(p0);
            ar[1] = *(const float4*)(p0 + 4);
            ar[2] = *(const float4*)(p1);
            ar[3] = *(const float4*)(p1 + 4);
        }
        const float* q0 = Bb + (k0 + 2 * b_kp) * (long)ldb + colBlk + b_c;
        br[0] = *(const float4*)(q0);
        br[1] = *(const float4*)(q0 + ldb);
    };

    auto stTile = [&]() {
        if (!TRANS_A) {
            // pack consecutive-k pairs within this thread's 16 floats
            float av[16] = {ar[0].x, ar[0].y, ar[0].z, ar[0].w,
                            ar[1].x, ar[1].y, ar[1].z, ar[1].w,
                            ar[2].x, ar[2].y, ar[2].z, ar[2].w,
                            ar[3].x, ar[3].y, ar[3].z, ar[3].w};
            unsigned* dh = &AsH[a_row][a_kb >> 1];
            unsigned* dl = &AsL[a_row][a_kb >> 1];
            #pragma unroll
            for (int i = 0; i < 8; i++) splitpack(av[2 * i], av[2 * i + 1], dh[i], dl[i]);
        } else {
            // rows k, k+1 for 8 m-values: pack across the two k rows
            float r0[8] = {ar[0].x, ar[0].y, ar[0].z, ar[0].w,
                           ar[1].x, ar[1].y, ar[1].z, ar[1].w};
            float r1[8] = {ar[2].x, ar[2].y, ar[2].z, ar[2].w,
                           ar[3].x, ar[3].y, ar[3].z, ar[3].w};
            #pragma unroll
            for (int i = 0; i < 8; i++) {
                unsigned h, l;
                splitpack(r0[i], r1[i], h, l);
                AsH[at_m0 + i][at_kp] = h;
                AsL[at_m0 + i][at_kp] = l;
            }
        }
        float b0[4] = {br[0].x, br[0].y, br[0].z, br[0].w};
        float b1[4] = {br[1].x, br[1].y, br[1].z, br[1].w};
        unsigned* eh = &BsH[b_kp][b_c];
        unsigned* el = &BsL[b_kp][b_c];
        #pragma unroll
        for (int j = 0; j < 4; j++) splitpack(b0[j], b1[j], eh[j], el[j]);
    };

    int wid = tid >> 5, lane = tid & 31;
    int gid = lane >> 2, tig = lane & 3;
    int wm = wid >> 1, wn = wid & 1;
    int wrow = wm * 32, wcol = wn * 32;

    float acc[2][4][4] = {};

    int nT = Ksz / BK;
    ldTile(0);
    for (int t = 0; t < nT; t++) {
        stTile();
        __syncthreads();
        if (t + 1 < nT) ldTile((long)(t + 1) * BK);
        #pragma unroll
        for (int kk = 0; kk < 2; kk++) {       // two k16 slices per BK=32
            int kb = kk * 8;                    // packed-u32 base
            unsigned afh[2][4], afl[2][4], bfh[4][2], bfl[4][2];
            #pragma unroll
            for (int mi = 0; mi < 2; mi++) {
                int r = wrow + mi * 16 + gid;
                afh[mi][0] = AsH[r][kb + tig];
                afh[mi][1] = AsH[r + 8][kb + tig];
                afh[mi][2] = AsH[r][kb + tig + 4];
                afh[mi][3] = AsH[r + 8][kb + tig + 4];
                afl[mi][0] = AsL[r][kb + tig];
                afl[mi][1] = AsL[r + 8][kb + tig];
                afl[mi][2] = AsL[r][kb + tig + 4];
                afl[mi][3] = AsL[r + 8][kb + tig + 4];
            }
            #pragma unroll
            for (int ni = 0; ni < 4; ni++) {
                int c = wcol + ni * 8 + gid;
                bfh[ni][0] = BsH[kb + tig][c];
                bfh[ni][1] = BsH[kb + tig + 4][c];
                bfl[ni][0] = BsL[kb + tig][c];
                bfl[ni][1] = BsL[kb + tig + 4][c];
            }
            #pragma unroll
            for (int mi = 0; mi < 2; mi++)
                #pragma unroll
                for (int ni = 0; ni < 4; ni++) {
                    mma_bf16(acc[mi][ni], afl[mi], bfh[ni]);
                    mma_bf16(acc[mi][ni], afh[mi], bfl[ni]);
                    mma_bf16(acc[mi][ni], afh[mi], bfh[ni]);
                }
        }
        __syncthreads();
    }

    // Epilogue
    float* Cb = C + (long)b * batchC;
    #pragma unroll
    for (int mi = 0; mi < 2; mi++) {
        #pragma unroll
        for (int ni = 0; ni < 4; ni++) {
            int r0 = rowBlk + wrow + mi * 16 + gid;
            int c0 = colBlk + wcol + ni * 8 + tig * 2;
            #pragma unroll
            for (int h = 0; h < 2; h++) {
                int r = r0 + h * 8;
                float v0 = acc[mi][ni][h * 2 + 0];
                float v1 = acc[mi][ni][h * 2 + 1];
                long o = (long)r * ldc + c0;
                if (EPI == 1) {
                    float bias = sq[r];
                    Cb[o]     = expf(v0 * PROJ_SCALE - bias) * RSQ_M;
                    Cb[o + 1] = expf(v1 * PROJ_SCALE - bias) * RSQ_M;
                } else if (EPI == 2) {
                    atomicAdd(&Cb[o], v0);
                    atomicAdd(&Cb[o + 1], v1);
                } else { // EPI == 3
                    float inv = 1.0f / den[b * Ln + r];
                    float fa0 = v0 * inv, fa1 = v1 * inv;
                    long go = (long)b * batchC + o;
                    C[go]     = content[go] + fa0;
                    C[go + 1] = content[go + 1] + fa1;
                    out2[go]     = fa0;
                    out2[go + 1] = fa1;
                }
            }
        }
    }
}

// ---------------------------------------------------------------------------
// Z[b][m] = sum_k phi_k[b][k][m]
// ---------------------------------------------------------------------------
__global__ void z_kernel(const float* __restrict__ PhiK, float* __restrict__ Z)
{
    int b = blockIdx.x, chunk = blockIdx.y, m = threadIdx.x;
    const float* p = PhiK + ((long)b * KLn + (long)chunk * 256) * Mf + m;
    float s = 0.f;
    #pragma unroll 8
    for (int k = 0; k < 256; k++) s += p[(long)k * Mf];
    atomicAdd(&Z[b * Mf + m], s);
}

// ---------------------------------------------------------------------------
// den[row] = dot(phi_q[row], Z[b]) + eps.  One warp per row.
// ---------------------------------------------------------------------------
__global__ void den_kernel(const float* __restrict__ PhiQ, const float* __restrict__ Z,
                           float* __restrict__ den)
{
    int row  = blockIdx.x * 8 + (threadIdx.x >> 5);
    int lane = threadIdx.x & 31;
    int b = row / Ln;
    const float4* pq = (const float4*)(PhiQ + (long)row * Mf);
    const float4* zz = (const float4*)(Z + b * Mf);
    float s = 0.f;
    #pragma unroll
    for (int i = lane; i < Mf / 4; i += 32) {
        float4 p = pq[i], q = zz[i];
        s += p.x * q.x + p.y * q.y + p.z * q.z + p.w * q.w;
    }
    #pragma unroll
    for (int o = 16; o; o >>= 1) s += __shfl_xor_sync(0xffffffffu, s, o);
    if (lane == 0) den[row] = s + 1e-8f;
}

// ---------------------------------------------------------------------------
// Launch
// ---------------------------------------------------------------------------
#define SPLIT_S 4

extern "C" void kernel_launch(void* const* d_in, const int* in_sizes, int n_in,
                              void* d_out, int out_size)
{
    const float* content = (const float*)d_in[0];
    const float* style   = (const float*)d_in[1];
    const float* W       = (const float*)d_in[2];
    float* out = (float*)d_out;

    float *phi_q, *phi_k, *sqq, *sqk, *Z, *S, *den;
    cudaGetSymbolAddress((void**)&phi_q, g_phi_q);
    cudaGetSymbolAddress((void**)&phi_k, g_phi_k);
    cudaGetSymbolAddress((void**)&sqq,   g_sq_q);
    cudaGetSymbolAddress((void**)&sqk,   g_sq_k);
    cudaGetSymbolAddress((void**)&Z,     g_Z);
    cudaGetSymbolAddress((void**)&S,     g_S);
    cudaGetSymbolAddress((void**)&den,   g_den);

    // 1) row sum-of-squares
    rowsumsq_kernel<<<ROWS_Q / 8, 256>>>(content, sqq, ROWS_Q);
    rowsumsq_kernel<<<ROWS_K / 8, 256>>>(style, sqk, ROWS_K);

    // 2) zero S and Z
    zero_kernel<<<(Bn * Mf * Dn) / 256, 256>>>(S, Z);

    // 3) phi_q = phi(content @ W)   [16384,512]@[512,256]
    {
        dim3 g(Mf / BN, ROWS_Q / BM, 1);
        mma_gemm<0, 1><<<g, 256>>>(content, W, phi_q, Dn, Dn, Mf, Mf,
                                   0, 0, 0, 1, sqq, nullptr, nullptr, nullptr);
    }
    // 4) phi_k = phi(style @ W)     [65536,512]@[512,256]
    {
        dim3 g(Mf / BN, ROWS_K / BM, 1);
        mma_gemm<0, 1><<<g, 256>>>(style, W, phi_k, Dn, Dn, Mf, Mf,
                                   0, 0, 0, 1, sqk, nullptr, nullptr, nullptr);
    }
    // 5) Z = colsum(phi_k) per batch
    z_kernel<<<dim3(Bn, 32), 256>>>(phi_k, Z);

    // 6) S[b] = phi_k[b]^T @ style[b]  (split-K atomics)  [256,8192]^T@[8192,512]
    {
        dim3 g(Dn / BN, Mf / BM, Bn * SPLIT_S);
        mma_gemm<1, 2><<<g, 256>>>(phi_k, style, S, KLn / SPLIT_S, Mf, Dn, Dn,
                                   (long)KLn * Mf, (long)KLn * Dn, (long)Mf * Dn,
                                   SPLIT_S, nullptr, nullptr, nullptr, nullptr);
    }
    // 7) den = phi_q . Z + eps
    den_kernel<<<ROWS_Q / 8, 256>>>(phi_q, Z, den);

    // 8) num GEMM with fused final epilogue: out = content + fa, out2 = fa
    {
        dim3 g(Dn / BN, Ln / BM, Bn);
        mma_gemm<0, 3><<<g, 256>>>(phi_q, S, out, Mf, Mf, Dn, Dn,
                                   (long)Ln * Mf, (long)Mf * Dn, (long)Ln * Dn,
                                   1, nullptr, den, content, out + (long)ROWS_Q * Dn);
    }
}

// round 7
// speedup vs baseline: 2.2130x; 1.3523x over previous
#include <cuda_runtime.h>
#include <cuda_bf16.h>
#include <math.h>
#include <stdint.h>

// Problem constants (B=8, L=2048, D=512, K=4, m=256)
#define Bn 8
#define Ln 2048
#define Dn 512
#define Mf 256
#define KLn 8192
#define ROWS_Q 16384
#define ROWS_K 65536

// ------- global scratch: bf16 hi/lo PAIR-PACKED u32 arrays -------------------
// A-operands: [row][kpair]  (pair over last axis, low16 = even k)
// B-operands: [kpair][n]    (pair over k rows,  low16 = even k)
__device__ unsigned g_cpA_h[(size_t)ROWS_Q*(Dn/2)];     // content A
__device__ unsigned g_cpA_l[(size_t)ROWS_Q*(Dn/2)];
__device__ unsigned g_spA_h[(size_t)ROWS_K*(Dn/2)];     // style A
__device__ unsigned g_spA_l[(size_t)ROWS_K*(Dn/2)];
__device__ unsigned g_wB_h[(size_t)(Dn/2)*Mf];          // W as B
__device__ unsigned g_wB_l[(size_t)(Dn/2)*Mf];
__device__ unsigned g_spB_h[(size_t)(ROWS_K/2)*Dn];     // style as B
__device__ unsigned g_spB_l[(size_t)(ROWS_K/2)*Dn];
__device__ unsigned g_pq_h[(size_t)ROWS_Q*(Mf/2)];      // phi_q (A of final)
__device__ unsigned g_pq_l[(size_t)ROWS_Q*(Mf/2)];
__device__ unsigned g_pk_h[(size_t)ROWS_K*(Mf/2)];      // phi_k [kl][mpair]
__device__ unsigned g_pk_l[(size_t)ROWS_K*(Mf/2)];
__device__ unsigned g_pkT_h[(size_t)Bn*Mf*(KLn/2)];     // phi_k^T [m][klpair]
__device__ unsigned g_pkT_l[(size_t)Bn*Mf*(KLn/2)];
__device__ unsigned g_sB_h[(size_t)(Bn*Mf/2)*Dn];       // S as B
__device__ unsigned g_sB_l[(size_t)(Bn*Mf/2)*Dn];
__device__ float g_S[(size_t)Bn*Mf*Dn];
__device__ float g_Z[Bn*Mf];
__device__ float g_den[ROWS_Q];
__device__ float g_sq_q[ROWS_Q];
__device__ float g_sq_k[ROWS_K];

__device__ __constant__ float PROJ_SCALE = 0.21022410381342864f;  // 512^-0.25
__device__ __constant__ float SQ_SCALE   = 0.022097086912079608f; // 1/(2*sqrt(512))
__device__ __constant__ float RSQ_M      = 0.0625f;               // 256^-0.5

// ---------------- helpers ----------------------------------------------------
__device__ __forceinline__ uint32_t smem_addr(const void* p) {
    uint32_t a;
    asm("{ .reg .u64 t; cvta.to.shared.u64 t, %1; cvt.u32.u64 %0, t; }" : "=r"(a) : "l"(p));
    return a;
}
__device__ __forceinline__ void split1(float x, unsigned short& h, unsigned short& l) {
    __nv_bfloat16 hb = __float2bfloat16_rn(x);
    h = __bfloat16_as_ushort(hb);
    l = __bfloat16_as_ushort(__float2bfloat16_rn(x - __bfloat162float(hb)));
}
__device__ __forceinline__ float bfu(unsigned short u) {
    return __bfloat162float(__ushort_as_bfloat16(u));
}
// pack bf16 of (a=even k, b=odd k): low16 = a
__device__ __forceinline__ void packpair(float a, float b, unsigned& h, unsigned& l) {
    unsigned short ha, la, hb, lb;
    split1(a, ha, la); split1(b, hb, lb);
    h = (unsigned)ha | ((unsigned)hb << 16);
    l = (unsigned)la | ((unsigned)lb << 16);
}
__device__ __forceinline__ void cp16(uint32_t d, const void* g) {
    asm volatile("cp.async.cg.shared.global [%0], [%1], 16;" :: "r"(d), "l"(g));
}
__device__ __forceinline__ void mma_bf16(float c[4], const unsigned a[4], const unsigned b[2]) {
    asm volatile(
        "mma.sync.aligned.m16n8k16.row.col.f32.bf16.bf16.f32 "
        "{%0,%1,%2,%3}, {%4,%5,%6,%7}, {%8,%9}, {%0,%1,%2,%3};\n"
        : "+f"(c[0]), "+f"(c[1]), "+f"(c[2]), "+f"(c[3])
        : "r"(a[0]), "r"(a[1]), "r"(a[2]), "r"(a[3]), "r"(b[0]), "r"(b[1]));
}

// ---------------------------------------------------------------------------
// rowsumsq + A-pack (pairs over d): one warp per row
// ---------------------------------------------------------------------------
__global__ void rowsumsq_pack(const float* __restrict__ X, float* __restrict__ sq,
                              unsigned* __restrict__ OH, unsigned* __restrict__ OL,
                              int rows)
{
    int row  = blockIdx.x * 8 + (threadIdx.x >> 5);
    int lane = threadIdx.x & 31;
    if (row >= rows) return;
    const float4* xp = (const float4*)(X + (long)row * Dn);
    float s = 0.f;
    #pragma unroll
    for (int i = lane; i < Dn / 4; i += 32) {
        float4 v = xp[i];
        s += v.x * v.x + v.y * v.y + v.z * v.z + v.w * v.w;
        uint2 hh, ll;
        packpair(v.x, v.y, hh.x, ll.x);
        packpair(v.z, v.w, hh.y, ll.y);
        *(uint2*)(OH + (long)row * (Dn/2) + i * 2) = hh;
        *(uint2*)(OL + (long)row * (Dn/2) + i * 2) = ll;
    }
    #pragma unroll
    for (int o = 16; o; o >>= 1) s += __shfl_xor_sync(0xffffffffu, s, o);
    if (lane == 0) sq[row] = s * SQ_SCALE;
}

// ---------------------------------------------------------------------------
// B-pack: dst[kp][n] = pack(src[2kp][n], src[2kp+1][n]); src fp32 [K][N]
// ---------------------------------------------------------------------------
__global__ void packB_rows(const float* __restrict__ src,
                           unsigned* __restrict__ dh, unsigned* __restrict__ dl,
                           int N, long nQuads)
{
    long t = (long)blockIdx.x * 256 + threadIdx.x;
    if (t >= nQuads) return;
    long kp = t / (N / 4);
    int  c4 = (int)(t % (N / 4)) * 4;
    float4 r0 = *(const float4*)(src + (2 * kp) * (long)N + c4);
    float4 r1 = *(const float4*)(src + (2 * kp + 1) * (long)N + c4);
    float a0[4] = {r0.x, r0.y, r0.z, r0.w};
    float a1[4] = {r1.x, r1.y, r1.z, r1.w};
    uint4 hq, lq;
    unsigned* hp = (unsigned*)&hq; unsigned* lp = (unsigned*)&lq;
    #pragma unroll
    for (int i = 0; i < 4; i++) packpair(a0[i], a1[i], hp[i], lp[i]);
    *(uint4*)(dh + kp * N + c4) = hq;
    *(uint4*)(dl + kp * N + c4) = lq;
}

// ---------------------------------------------------------------------------
// transpose-pack phi_k: src u32 [b*KLn + kl][Mf/2] (pairs over m)
//                    -> dst u32 [b][m][KLn/2]      (pairs over kl)
// tile: 64 kl x 64 m per block
// ---------------------------------------------------------------------------
__global__ void transpack(const unsigned* __restrict__ sh_, const unsigned* __restrict__ sl_,
                          unsigned* __restrict__ dh, unsigned* __restrict__ dl)
{
    __shared__ unsigned Th[64][33], Tl[64][33];
    int tk = blockIdx.x, tm = blockIdx.y, b = blockIdx.z;
    const unsigned* sh = sh_ + ((long)b * KLn + tk * 64) * (Mf/2) + tm * 32;
    const unsigned* sl = sl_ + ((long)b * KLn + tk * 64) * (Mf/2) + tm * 32;
    int r = threadIdx.x >> 3, c4 = (threadIdx.x & 7) * 4;
    {
        uint4 v = *(const uint4*)(sh + (long)r * (Mf/2) + c4);
        Th[r][c4] = v.x; Th[r][c4+1] = v.y; Th[r][c4+2] = v.z; Th[r][c4+3] = v.w;
        v = *(const uint4*)(sh + (long)(r + 32) * (Mf/2) + c4);
        Th[r+32][c4] = v.x; Th[r+32][c4+1] = v.y; Th[r+32][c4+2] = v.z; Th[r+32][c4+3] = v.w;
        v = *(const uint4*)(sl + (long)r * (Mf/2) + c4);
        Tl[r][c4] = v.x; Tl[r][c4+1] = v.y; Tl[r][c4+2] = v.z; Tl[r][c4+3] = v.w;
        v = *(const uint4*)(sl + (long)(r + 32) * (Mf/2) + c4);
        Tl[r+32][c4] = v.x; Tl[r+32][c4+1] = v.y; Tl[r+32][c4+2] = v.z; Tl[r+32][c4+3] = v.w;
    }
    __syncthreads();
    int m = threadIdx.x >> 2;            // 0..63 local m
    int kj = (threadIdx.x & 3) * 8;      // klp base 0,8,16,24
    int mp = m >> 1, pm = m & 1;
    unsigned oh[8], ol[8];
    #pragma unroll
    for (int j = 0; j < 8; j++) {
        int klp = kj + j;
        unsigned t0 = Th[2*klp][mp],   t1 = Th[2*klp+1][mp];
        unsigned u0 = Tl[2*klp][mp],   u1 = Tl[2*klp+1][mp];
        unsigned e0 = pm ? (t0 >> 16) : (t0 & 0xffff);
        unsigned e1 = pm ? (t1 >> 16) : (t1 & 0xffff);
        oh[j] = e0 | (e1 << 16);
        unsigned f0 = pm ? (u0 >> 16) : (u0 & 0xffff);
        unsigned f1 = pm ? (u1 >> 16) : (u1 & 0xffff);
        ol[j] = f0 | (f1 << 16);
    }
    long o = (long)b * Mf * (KLn/2) + (long)(tm * 64 + m) * (KLn/2) + tk * 32 + kj;
    *(uint4*)(dh + o)     = make_uint4(oh[0], oh[1], oh[2], oh[3]);
    *(uint4*)(dh + o + 4) = make_uint4(oh[4], oh[5], oh[6], oh[7]);
    *(uint4*)(dl + o)     = make_uint4(ol[0], ol[1], ol[2], ol[3]);
    *(uint4*)(dl + o + 4) = make_uint4(ol[4], ol[5], ol[6], ol[7]);
}

__global__ void zero_kernel(float* __restrict__ S, float* __restrict__ Z)
{
    long i = (long)blockIdx.x * 256 + threadIdx.x;
    if (i < (long)Bn * Mf * Dn) S[i] = 0.f;
    if (i < Bn * Mf)            Z[i] = 0.f;
}

// ---------------------------------------------------------------------------
// bf16x2-compensated GEMM, round-5 fragment logic + cp.async double buffer.
//   C tile 128x64, BK=32, 8 warps (4x2), warp tile 32x32.
//   A: u32 [row][kpair] (ldaP pairs). B: u32 [kpair][n] (ldbB).
//   EPI=1: phi epilogue -> pair-packed OH/OL
//   EPI=2: atomicAdd fp32 into C (split-K)
//   EPI=3: fused final
// ---------------------------------------------------------------------------
#define STG_U32 7296   // AH 2560 | AL 2560 | BH 1088 | BL 1088
#define SMEM_BYTES (2 * STG_U32 * 4)

template<int EPI>
__global__ void __launch_bounds__(256)
tc_gemm(const unsigned* __restrict__ Ah, const unsigned* __restrict__ Al,
        const unsigned* __restrict__ Bh, const unsigned* __restrict__ Bl,
        float* __restrict__ C, int Ksz, int ldaP, int ldbB, int ldc,
        long batchA, long batchB, long batchC, int splitK,
        const float* __restrict__ sq,
        unsigned* __restrict__ OH, unsigned* __restrict__ OL,
        const float* __restrict__ den, const float* __restrict__ content,
        float* __restrict__ out2)
{
    extern __shared__ unsigned sm[];

    int bz = blockIdx.z;
    int b  = bz / splitK;
    int sp = bz % splitK;
    long kBegP = (long)sp * (Ksz / 2);

    const unsigned* Agh = Ah + (long)b * batchA + kBegP;
    const unsigned* Agl = Al + (long)b * batchA + kBegP;
    const unsigned* Bgh = Bh + (long)b * batchB + kBegP * ldbB;
    const unsigned* Bgl = Bl + (long)b * batchB + kBegP * ldbB;

    int rowBlk = blockIdx.y * 128;
    int colBlk = blockIdx.x * 64;
    int tid = threadIdx.x, wid = tid >> 5, lane = tid & 31;
    int gid = lane >> 2, tig = lane & 3;
    int wm = wid >> 1, wn = wid & 1;
    int wrow = wm * 32, wcol = wn * 32;

    auto loadStage = [&](int t, int s) {
        unsigned* AH = sm + s * STG_U32;
        unsigned* AL = AH + 2560;
        unsigned* BH = AH + 5120;
        unsigned* BL = AH + 6208;
        int kp0 = t * 16;
        {
            int r = tid >> 1, half = tid & 1;
            const unsigned* gh = Agh + (long)(rowBlk + r) * ldaP + kp0 + half * 8;
            const unsigned* gl = Agl + (long)(rowBlk + r) * ldaP + kp0 + half * 8;
            uint32_t dh = smem_addr(AH + r * 20 + half * 8);
            uint32_t dl = smem_addr(AL + r * 20 + half * 8);
            cp16(dh, gh); cp16(dh + 16, gh + 4);
            cp16(dl, gl); cp16(dl + 16, gl + 4);
        }
        {
            int rr = tid >> 4, cc = tid & 15;
            const unsigned* gh = Bgh + (long)(kp0 + rr) * ldbB + colBlk + cc * 4;
            const unsigned* gl = Bgl + (long)(kp0 + rr) * ldbB + colBlk + cc * 4;
            cp16(smem_addr(BH + rr * 68 + cc * 4), gh);
            cp16(smem_addr(BL + rr * 68 + cc * 4), gl);
        }
    };

    float acc[2][4][4] = {};
    int nT = Ksz / 32;

    loadStage(0, 0);
    asm volatile("cp.async.commit_group;" ::: "memory");

    for (int t = 0; t < nT; t++) {
        __syncthreads();   // all warps done with buf (t+1)&1 from iteration t-1
        if (t + 1 < nT) {
            loadStage(t + 1, (t + 1) & 1);
            asm volatile("cp.async.commit_group;" ::: "memory");
            asm volatile("cp.async.wait_group 1;" ::: "memory");
        } else {
            asm volatile("cp.async.wait_group 0;" ::: "memory");
        }
        __syncthreads();

        unsigned* AH = sm + (t & 1) * STG_U32;
        unsigned* AL = AH + 2560;
        unsigned* BH = AH + 5120;
        unsigned* BL = AH + 6208;

        #pragma unroll
        for (int kk = 0; kk < 2; kk++) {
            int kb = kk * 8;
            unsigned afh[2][4], afl[2][4], bfh[4][2], bfl[4][2];
            #pragma unroll
            for (int mi = 0; mi < 2; mi++) {
                int r = wrow + mi * 16 + gid;
                afh[mi][0] = AH[r * 20 + kb + tig];
                afh[mi][1] = AH[(r + 8) * 20 + kb + tig];
                afh[mi][2] = AH[r * 20 + kb + tig + 4];
                afh[mi][3] = AH[(r + 8) * 20 + kb + tig + 4];
                afl[mi][0] = AL[r * 20 + kb + tig];
                afl[mi][1] = AL[(r + 8) * 20 + kb + tig];
                afl[mi][2] = AL[r * 20 + kb + tig + 4];
                afl[mi][3] = AL[(r + 8) * 20 + kb + tig + 4];
            }
            #pragma unroll
            for (int ni = 0; ni < 4; ni++) {
                int c = wcol + ni * 8 + gid;
                bfh[ni][0] = BH[(kb + tig) * 68 + c];
                bfh[ni][1] = BH[(kb + tig + 4) * 68 + c];
                bfl[ni][0] = BL[(kb + tig) * 68 + c];
                bfl[ni][1] = BL[(kb + tig + 4) * 68 + c];
            }
            #pragma unroll
            for (int mi = 0; mi < 2; mi++)
                #pragma unroll
                for (int ni = 0; ni < 4; ni++) {
                    mma_bf16(acc[mi][ni], afl[mi], bfh[ni]);
                    mma_bf16(acc[mi][ni], afh[mi], bfl[ni]);
                    mma_bf16(acc[mi][ni], afh[mi], bfh[ni]);
                }
        }
    }

    // ---- epilogue ----
    float* Cb = C + (long)b * batchC;
    #pragma unroll
    for (int mi = 0; mi < 2; mi++) {
        #pragma unroll
        for (int ni = 0; ni < 4; ni++) {
            int r0 = rowBlk + wrow + mi * 16 + gid;
            int c0 = colBlk + wcol + ni * 8 + tig * 2;
            #pragma unroll
            for (int h = 0; h < 2; h++) {
                int r = r0 + h * 8;
                float v0 = acc[mi][ni][h * 2 + 0];
                float v1 = acc[mi][ni][h * 2 + 1];
                if (EPI == 1) {
                    float bias = sq[r];
                    float p0 = expf(v0 * PROJ_SCALE - bias) * RSQ_M;
                    float p1 = expf(v1 * PROJ_SCALE - bias) * RSQ_M;
                    unsigned hh, ll;
                    packpair(p0, p1, hh, ll);
                    long o = (long)r * (ldc / 2) + c0 / 2;
                    OH[o] = hh; OL[o] = ll;
                } else if (EPI == 2) {
                    long o = (long)r * ldc + c0;
                    atomicAdd(&Cb[o], v0);
                    atomicAdd(&Cb[o + 1], v1);
                } else {
                    float inv = 1.0f / den[b * Ln + r];
                    float fa0 = v0 * inv, fa1 = v1 * inv;
                    long go = (long)b * batchC + (long)r * ldc + c0;
                    C[go]     = content[go] + fa0;
                    C[go + 1] = content[go + 1] + fa1;
                    out2[go]     = fa0;
                    out2[go + 1] = fa1;
                }
            }
        }
    }
}

// ---------------------------------------------------------------------------
// Z[b][m] = sum_kl phi_k; pk is u32 [kl][Mf/2] (pairs over m)
// ---------------------------------------------------------------------------
__global__ void z_kernel(const unsigned* __restrict__ ph, const unsigned* __restrict__ pl,
                         float* __restrict__ Z)
{
    int b = blockIdx.x, chunk = blockIdx.y;
    int cp = threadIdx.x & 127, half = threadIdx.x >> 7;
    const unsigned* rh = ph + ((long)b * KLn + chunk * 256 + half * 128) * (Mf/2) + cp;
    const unsigned* rl = pl + ((long)b * KLn + chunk * 256 + half * 128) * (Mf/2) + cp;
    float s0 = 0.f, s1 = 0.f;
    #pragma unroll 4
    for (int k = 0; k < 128; k++) {
        unsigned h = rh[(long)k * 128], l = rl[(long)k * 128];
        s0 += bfu((unsigned short)(h & 0xffff)) + bfu((unsigned short)(l & 0xffff));
        s1 += bfu((unsigned short)(h >> 16))    + bfu((unsigned short)(l >> 16));
    }
    atomicAdd(&Z[b * Mf + cp * 2],     s0);
    atomicAdd(&Z[b * Mf + cp * 2 + 1], s1);
}

__global__ void den_kernel(const unsigned* __restrict__ ph, const unsigned* __restrict__ pl,
                           const float* __restrict__ Z, float* __restrict__ den)
{
    int row  = blockIdx.x * 8 + (threadIdx.x >> 5);
    int lane = threadIdx.x & 31;
    int b = row / Ln;
    uint4 h = ((const uint4*)(ph + (long)row * (Mf/2)))[lane];
    uint4 l = ((const uint4*)(pl + (long)row * (Mf/2)))[lane];
    const float* z = Z + b * Mf + lane * 8;
    unsigned hw[4] = {h.x, h.y, h.z, h.w};
    unsigned lw[4] = {l.x, l.y, l.z, l.w};
    float s = 0.f;
    #pragma unroll
    for (int j = 0; j < 4; j++) {
        s += (bfu((unsigned short)(hw[j] & 0xffff)) + bfu((unsigned short)(lw[j] & 0xffff))) * z[2*j];
        s += (bfu((unsigned short)(hw[j] >> 16))    + bfu((unsigned short)(lw[j] >> 16)))    * z[2*j+1];
    }
    #pragma unroll
    for (int o = 16; o; o >>= 1) s += __shfl_xor_sync(0xffffffffu, s, o);
    if (lane == 0) den[row] = s + 1e-8f;
}

// ---------------------------------------------------------------------------
#define SPLIT_S 4

extern "C" void kernel_launch(void* const* d_in, const int* in_sizes, int n_in,
                              void* d_out, int out_size)
{
    const float* content = (const float*)d_in[0];
    const float* style   = (const float*)d_in[1];
    const float* W       = (const float*)d_in[2];
    float* out = (float*)d_out;

    unsigned *cpAh,*cpAl,*spAh,*spAl,*wBh,*wBl,*spBh,*spBl,*pqh,*pql,*pkh,*pkl,*pkTh,*pkTl,*sBh,*sBl;
    float *S, *Z, *den, *sqq, *sqk;
    cudaGetSymbolAddress((void**)&cpAh, g_cpA_h);  cudaGetSymbolAddress((void**)&cpAl, g_cpA_l);
    cudaGetSymbolAddress((void**)&spAh, g_spA_h);  cudaGetSymbolAddress((void**)&spAl, g_spA_l);
    cudaGetSymbolAddress((void**)&wBh,  g_wB_h);   cudaGetSymbolAddress((void**)&wBl,  g_wB_l);
    cudaGetSymbolAddress((void**)&spBh, g_spB_h);  cudaGetSymbolAddress((void**)&spBl, g_spB_l);
    cudaGetSymbolAddress((void**)&pqh,  g_pq_h);   cudaGetSymbolAddress((void**)&pql,  g_pq_l);
    cudaGetSymbolAddress((void**)&pkh,  g_pk_h);   cudaGetSymbolAddress((void**)&pkl,  g_pk_l);
    cudaGetSymbolAddress((void**)&pkTh, g_pkT_h);  cudaGetSymbolAddress((void**)&pkTl, g_pkT_l);
    cudaGetSymbolAddress((void**)&sBh,  g_sB_h);   cudaGetSymbolAddress((void**)&sBl,  g_sB_l);
    cudaGetSymbolAddress((void**)&S,    g_S);
    cudaGetSymbolAddress((void**)&Z,    g_Z);
    cudaGetSymbolAddress((void**)&den,  g_den);
    cudaGetSymbolAddress((void**)&sqq,  g_sq_q);
    cudaGetSymbolAddress((void**)&sqk,  g_sq_k);

    cudaFuncSetAttribute(tc_gemm<1>, cudaFuncAttributeMaxDynamicSharedMemorySize, SMEM_BYTES);
    cudaFuncSetAttribute(tc_gemm<2>, cudaFuncAttributeMaxDynamicSharedMemorySize, SMEM_BYTES);
    cudaFuncSetAttribute(tc_gemm<3>, cudaFuncAttributeMaxDynamicSharedMemorySize, SMEM_BYTES);

    // 1) sum-of-squares + A-pack
    rowsumsq_pack<<<ROWS_Q / 8, 256>>>(content, sqq, cpAh, cpAl, ROWS_Q);
    rowsumsq_pack<<<ROWS_K / 8, 256>>>(style, sqk, spAh, spAl, ROWS_K);

    // 2) B-packs: W and style (pairs over k rows)
    packB_rows<<<((long)(Dn/2) * (Mf/4) + 255) / 256, 256>>>(W, wBh, wBl, Mf, (long)(Dn/2) * (Mf/4));
    packB_rows<<<((long)(ROWS_K/2) * (Dn/4) + 255) / 256, 256>>>(style, spBh, spBl, Dn, (long)(ROWS_K/2) * (Dn/4));

    // 3) zero S, Z
    zero_kernel<<<(Bn * Mf * Dn) / 256, 256>>>(S, Z);

    // 4) phi_q = phi(content @ W)
    tc_gemm<1><<<dim3(Mf/64, ROWS_Q/128, 1), 256, SMEM_BYTES>>>(
        cpAh, cpAl, wBh, wBl, nullptr, Dn, Dn/2, Mf, Mf,
        0, 0, 0, 1, sqq, pqh, pql, nullptr, nullptr, nullptr);

    // 5) phi_k = phi(style @ W)
    tc_gemm<1><<<dim3(Mf/64, ROWS_K/128, 1), 256, SMEM_BYTES>>>(
        spAh, spAl, wBh, wBl, nullptr, Dn, Dn/2, Mf, Mf,
        0, 0, 0, 1, sqk, pkh, pkl, nullptr, nullptr, nullptr);

    // 6) Z = colsum(phi_k)
    z_kernel<<<dim3(Bn, 32), 256>>>(pkh, pkl, Z);

    // 7) transpose-pack phi_k -> pkT [b][m][klpair]
    transpack<<<dim3(KLn/64, Mf/64, Bn), 256>>>(pkh, pkl, pkTh, pkTl);

    // 8) S[b][m][d] = sum_kl phi_k^T * style  (split-K atomics)
    tc_gemm<2><<<dim3(Dn/64, Mf/128, Bn * SPLIT_S), 256, SMEM_BYTES>>>(
        pkTh, pkTl, spBh, spBl, S, KLn/SPLIT_S, KLn/2, Dn, Dn,
        (long)Mf * (KLn/2), (long)(KLn/2) * Dn, (long)Mf * Dn, SPLIT_S,
        nullptr, nullptr, nullptr, nullptr, nullptr, nullptr);

    // 9) pack S as B (pairs over m rows)
    packB_rows<<<((long)(Bn*Mf/2) * (Dn/4) + 255) / 256, 256>>>(S, sBh, sBl, Dn, (long)(Bn*Mf/2) * (Dn/4));

    // 10) den
    den_kernel<<<ROWS_Q / 8, 256>>>(pqh, pql, Z, den);

    // 11) num GEMM fused final
    tc_gemm<3><<<dim3(Dn/64, Ln/128, Bn), 256, SMEM_BYTES>>>(
        pqh, pql, sBh, sBl, out, Mf, Mf/2, Dn, Dn,
        (long)Ln * (Mf/2), (long)(Mf/2) * Dn, (long)Ln * Dn, 1,
        nullptr, nullptr, nullptr, den, content, out + (long)ROWS_Q * Dn);
}

// round 9
// speedup vs baseline: 2.5044x; 1.1317x over previous
#include <cuda_runtime.h>
#include <cuda_bf16.h>
#include <math.h>
#include <stdint.h>

// Problem constants (B=8, L=2048, D=512, K=4, m=256)
#define Bn 8
#define Ln 2048
#define Dn 512
#define Mf 256
#define KLn 8192
#define ROWS_Q 16384
#define ROWS_K 65536

// ===========================================================================
// Canonical fragment layouts (u32 = bf16 pair, low16 = even k):
//  A: element (row r, kpair kp):  g=r>>4, b=(r&15)>>3, gid=r&7,
//     s=kp>>3, tig=kp&3, hi=(kp>>2)&1, j=b+2*hi
//     u32 index = ((g*SA + s)*32 + gid*4 + tig)*4 + j          (SA = K/16)
//  B: element (kp, col n): s=kp>>3, tig=kp&3, j=(kp>>2)&1, h=n>>3, gid=n&7
//     u32 index = ((s*(N/8) + h)*32 + gid*4 + tig)*2 + j
// ===========================================================================

__device__ unsigned g_cA_h[(size_t)(ROWS_Q/16)*32*128];      // content A canon
__device__ unsigned g_cA_l[(size_t)(ROWS_Q/16)*32*128];
__device__ unsigned g_sA_h[(size_t)(ROWS_K/16)*32*128];      // style A canon
__device__ unsigned g_sA_l[(size_t)(ROWS_K/16)*32*128];
__device__ unsigned g_wB_h[(size_t)32*32*64];                // W B canon
__device__ unsigned g_wB_l[(size_t)32*32*64];
__device__ unsigned g_spB_h[(size_t)Bn*512*64*64];           // style B canon
__device__ unsigned g_spB_l[(size_t)Bn*512*64*64];
__device__ unsigned g_pq_h[(size_t)ROWS_Q*(Mf/2)];           // phi_q std
__device__ unsigned g_pq_l[(size_t)ROWS_Q*(Mf/2)];
__device__ unsigned g_pqc_h[(size_t)(ROWS_Q/16)*16*128];     // phi_q A canon
__device__ unsigned g_pqc_l[(size_t)(ROWS_Q/16)*16*128];
__device__ unsigned g_pk_h[(size_t)ROWS_K*(Mf/2)];           // phi_k std
__device__ unsigned g_pk_l[(size_t)ROWS_K*(Mf/2)];
__device__ unsigned g_pkT_h[(size_t)Bn*16*512*128];          // phi_k^T A canon
__device__ unsigned g_pkT_l[(size_t)Bn*16*512*128];
__device__ unsigned g_sB_h[(size_t)Bn*16*64*64];             // S B canon
__device__ unsigned g_sB_l[(size_t)Bn*16*64*64];
__device__ float g_S[(size_t)Bn*Mf*Dn];
__device__ float g_Z[Bn*Mf];
__device__ float g_den[ROWS_Q];
__device__ float g_sq_q[ROWS_Q];
__device__ float g_sq_k[ROWS_K];

__device__ __constant__ float PROJ_SCALE = 0.21022410381342864f;  // 512^-0.25
__device__ __constant__ float SQ_SCALE   = 0.022097086912079608f; // 1/(2*sqrt(512))
__device__ __constant__ float RSQ_M      = 0.0625f;               // 256^-0.5

// ---------------- helpers ----------------------------------------------------
__device__ __forceinline__ uint32_t smem_addr(const void* p) {
    uint32_t a;
    asm("{ .reg .u64 t; cvta.to.shared.u64 t, %1; cvt.u32.u64 %0, t; }" : "=r"(a) : "l"(p));
    return a;
}
__device__ __forceinline__ void split1(float x, unsigned short& h, unsigned short& l) {
    __nv_bfloat16 hb = __float2bfloat16_rn(x);
    h = __bfloat16_as_ushort(hb);
    l = __bfloat16_as_ushort(__float2bfloat16_rn(x - __bfloat162float(hb)));
}
__device__ __forceinline__ float bfu(unsigned short u) {
    return __bfloat162float(__ushort_as_bfloat16(u));
}
__device__ __forceinline__ void packpair(float a, float b, unsigned& h, unsigned& l) {
    unsigned short ha, la, hb, lb;
    split1(a, ha, la); split1(b, hb, lb);
    h = (unsigned)ha | ((unsigned)hb << 16);
    l = (unsigned)la | ((unsigned)lb << 16);
}
__device__ __forceinline__ void cp16(uint32_t d, const void* g) {
    asm volatile("cp.async.cg.shared.global [%0], [%1], 16;" :: "r"(d), "l"(g));
}
__device__ __forceinline__ void mma_bf16(float c[4], const unsigned a[4], const unsigned b[2]) {
    asm volatile(
        "mma.sync.aligned.m16n8k16.row.col.f32.bf16.bf16.f32 "
        "{%0,%1,%2,%3}, {%4,%5,%6,%7}, {%8,%9}, {%0,%1,%2,%3};\n"
        : "+f"(c[0]), "+f"(c[1]), "+f"(c[2]), "+f"(c[3])
        : "r"(a[0]), "r"(a[1]), "r"(a[2]), "r"(a[3]), "r"(b[0]), "r"(b[1]));
}

// ---------------------------------------------------------------------------
// rowsumsq + canonical-A pack.  One warp handles rows r0 = 16*bid + w and
// r0+8; each lane owns one k16 slice s=lane and writes one 64B canonical
// window per (h,l).  grid = rows/16, block = 256. K = 512 -> SA = 32.
// ---------------------------------------------------------------------------
__global__ void rowsumsq_pack(const float* __restrict__ X, float* __restrict__ sq,
                              unsigned* __restrict__ OH, unsigned* __restrict__ OL)
{
    int g = blockIdx.x;
    int w = threadIdx.x >> 5;          // gid
    int s = threadIdx.x & 31;          // k16 slice
    int r0 = g * 16 + w;
    int r1 = r0 + 8;

    float f0[16], f1[16];
    {
        const float4* p0 = (const float4*)(X + (long)r0 * Dn + s * 16);
        const float4* p1 = (const float4*)(X + (long)r1 * Dn + s * 16);
        #pragma unroll
        for (int i = 0; i < 4; i++) {
            float4 v = p0[i];
            f0[4*i] = v.x; f0[4*i+1] = v.y; f0[4*i+2] = v.z; f0[4*i+3] = v.w;
            v = p1[i];
            f1[4*i] = v.x; f1[4*i+1] = v.y; f1[4*i+2] = v.z; f1[4*i+3] = v.w;
        }
    }
    float s0 = 0.f, s1 = 0.f;
    #pragma unroll
    for (int i = 0; i < 16; i++) { s0 += f0[i]*f0[i]; s1 += f1[i]*f1[i]; }
    #pragma unroll
    for (int o = 16; o; o >>= 1) {
        s0 += __shfl_xor_sync(0xffffffffu, s0, o);
        s1 += __shfl_xor_sync(0xffffffffu, s1, o);
    }
    if (s == 0) { sq[r0] = s0 * SQ_SCALE; sq[r1] = s1 * SQ_SCALE; }

    unsigned wh[16], wl[16];
    #pragma unroll
    for (int tig = 0; tig < 4; tig++) {
        #pragma unroll
        for (int q = 0; q < 4; q++) {
            int t = tig + 4 * (q >> 1);
            const float* f = (q & 1) ? f1 : f0;
            packpair(f[2*t], f[2*t+1], wh[tig*4+q], wl[tig*4+q]);
        }
    }
    long base = (((long)g * 32 + s) * 32 + w * 4) * 4;
    #pragma unroll
    for (int i = 0; i < 4; i++) {
        *(uint4*)(OH + base + i * 4) = make_uint4(wh[4*i], wh[4*i+1], wh[4*i+2], wh[4*i+3]);
        *(uint4*)(OL + base + i * 4) = make_uint4(wl[4*i], wl[4*i+1], wl[4*i+2], wl[4*i+3]);
    }
}

// ---------------------------------------------------------------------------
// Canonical-B pack from fp32 [K][N] (optionally batched).
// ---------------------------------------------------------------------------
__global__ void packB_canon(const float* __restrict__ src,
                            unsigned* __restrict__ dh, unsigned* __restrict__ dl,
                            int K, int N, long srcBatch, long dstBatchU2)
{
    long blk = (long)blockIdx.x * 8 + (threadIdx.x >> 5);
    int lane = threadIdx.x & 31;
    int gid = lane >> 2, tig = lane & 3;
    long perBatch = (long)(K / 16) * (N / 8);
    int bb = (int)(blk / perBatch);
    long rem = blk % perBatch;
    int s = (int)(rem / (N / 8));
    int h = (int)(rem % (N / 8));
    int n = h * 8 + gid;
    const float* sb = src + (long)bb * srcBatch;
    unsigned h0, l0, h1, l1;
    {
        int r = 16 * s + 2 * tig;
        packpair(sb[(long)r * N + n], sb[(long)(r + 1) * N + n], h0, l0);
        packpair(sb[(long)(r + 8) * N + n], sb[(long)(r + 9) * N + n], h1, l1);
    }
    long u2 = (long)bb * dstBatchU2 + ((long)s * (N / 8) + h) * 32 + lane;
    ((uint2*)dh)[u2] = make_uint2(h0, h1);
    ((uint2*)dl)[u2] = make_uint2(l0, l1);
}

// ---------------------------------------------------------------------------
// transpose-pack phi_k std [b*KLn + kl][Mf/2] -> canonical-A [b][m][kl] (SA=512)
// ---------------------------------------------------------------------------
__global__ void transpack(const unsigned* __restrict__ sh_, const unsigned* __restrict__ sl_,
                          unsigned* __restrict__ dh, unsigned* __restrict__ dl)
{
    __shared__ unsigned Th[64][33], Tl[64][33];
    int tk = blockIdx.x, tm = blockIdx.y, bb = blockIdx.z;
    const unsigned* sh = sh_ + ((long)bb * KLn + tk * 64) * (Mf/2) + tm * 32;
    const unsigned* sl = sl_ + ((long)bb * KLn + tk * 64) * (Mf/2) + tm * 32;
    int r = threadIdx.x >> 3, c4 = (threadIdx.x & 7) * 4;
    {
        uint4 v = *(const uint4*)(sh + (long)r * (Mf/2) + c4);
        Th[r][c4] = v.x; Th[r][c4+1] = v.y; Th[r][c4+2] = v.z; Th[r][c4+3] = v.w;
        v = *(const uint4*)(sh + (long)(r + 32) * (Mf/2) + c4);
        Th[r+32][c4] = v.x; Th[r+32][c4+1] = v.y; Th[r+32][c4+2] = v.z; Th[r+32][c4+3] = v.w;
        v = *(const uint4*)(sl + (long)r * (Mf/2) + c4);
        Tl[r][c4] = v.x; Tl[r][c4+1] = v.y; Tl[r][c4+2] = v.z; Tl[r][c4+3] = v.w;
        v = *(const uint4*)(sl + (long)(r + 32) * (Mf/2) + c4);
        Tl[r+32][c4] = v.x; Tl[r+32][c4+1] = v.y; Tl[r+32][c4+2] = v.z; Tl[r+32][c4+3] = v.w;
    }
    __syncthreads();
    int m = threadIdx.x >> 2;
    int kj = (threadIdx.x & 3) * 8;
    int mp = m >> 1, pm = m & 1;
    unsigned oh[8], ol[8];
    #pragma unroll
    for (int j = 0; j < 8; j++) {
        int klp = kj + j;
        unsigned t0 = Th[2*klp][mp],   t1 = Th[2*klp+1][mp];
        unsigned u0 = Tl[2*klp][mp],   u1 = Tl[2*klp+1][mp];
        unsigned e0 = pm ? (t0 >> 16) : (t0 & 0xffff);
        unsigned e1 = pm ? (t1 >> 16) : (t1 & 0xffff);
        oh[j] = e0 | (e1 << 16);
        unsigned f0 = pm ? (u0 >> 16) : (u0 & 0xffff);
        unsigned f1 = pm ? (u1 >> 16) : (u1 & 0xffff);
        ol[j] = f0 | (f1 << 16);
    }
    int mg = tm * 64 + m;
    int g = mg >> 4, b_ = (mg & 15) >> 3, gidw = mg & 7;
    int sS = (tk * 32 + kj) >> 3;
    long base = (long)bb * (16L * 512 * 128) + (((long)g * 512 + sS) * 32 + gidw * 4) * 4;
    #pragma unroll
    for (int j = 0; j < 8; j++) {
        int tig = j & 3, hi = j >> 2;
        long a = base + tig * 4 + b_ + 2 * hi;
        dh[a] = oh[j]; dl[a] = ol[j];
    }
}

__global__ void zero_kernel(float* __restrict__ S, float* __restrict__ Z)
{
    long i = (long)blockIdx.x * 256 + threadIdx.x;
    if (i < (long)Bn * Mf * Dn) S[i] = 0.f;
    if (i < Bn * Mf)            Z[i] = 0.f;
}

// ---------------------------------------------------------------------------
// Canonical-layout bf16x2-compensated GEMM.
//  C tile 128x64, BK=32, 8 warps (4x2), warp tile 32x32, cp.async dbl buffer.
//  Stage layout (u32): AH 0..2047 | AL 2048..4095 | BH 4096..5119 | BL 5120..6143
// ---------------------------------------------------------------------------
#define STG_U32 6144

template<int EPI>
__global__ void __launch_bounds__(256)
tc_gemm(const unsigned* __restrict__ Ah, const unsigned* __restrict__ Al,
        const unsigned* __restrict__ Bh, const unsigned* __restrict__ Bl,
        float* __restrict__ C, int Ksz, int SA, int Nt, int ldc, int SAout,
        long batchA, long batchB, long batchC, int splitK,
        const float* __restrict__ sq,
        unsigned* __restrict__ OH, unsigned* __restrict__ OL,
        unsigned* __restrict__ OH2, unsigned* __restrict__ OL2,
        const float* __restrict__ den, const float* __restrict__ content,
        float* __restrict__ out2)
{
    __shared__ __align__(16) unsigned sm[2 * STG_U32];

    int bz = blockIdx.z;
    int b  = bz / splitK;
    int sp = bz % splitK;
    int sBeg = sp * (Ksz / 16);

    const unsigned* Agh = Ah + (long)b * batchA;
    const unsigned* Agl = Al + (long)b * batchA;
    const unsigned* Bgh = Bh + (long)b * batchB;
    const unsigned* Bgl = Bl + (long)b * batchB;

    int rowBlk = blockIdx.y * 128;
    int colBlk = blockIdx.x * 64;
    int gA = rowBlk >> 4;
    int hA = colBlk >> 3;
    int tid = threadIdx.x, wid = tid >> 5, lane = tid & 31;
    int gid = lane >> 2, tig = lane & 3;
    int wm = wid >> 1, wn = wid & 1;

    auto loadStage = [&](int t, int st) {
        unsigned* base = sm + st * STG_U32;
        int s0 = sBeg + 2 * t;
        // A: 16 blocks of 512B (g_local 0..7 x s_local 0..1)
        {
            int blk = tid >> 4;
            int gl = blk >> 1, sl = blk & 1;
            long src = (((long)(gA + gl)) * SA + (s0 + sl)) * 128 + (tid & 15) * 8;
            uint32_t dst = smem_addr(base + blk * 128 + (tid & 15) * 8);
            cp16(dst,      Agh + src);
            cp16(dst + 16, Agh + src + 4);
            cp16(dst + 8192,      Agl + src);
            cp16(dst + 8192 + 16, Agl + src + 4);
        }
        // B: 16 blocks of 256B (s_local 0..1 x h_local 0..7)
        {
            int blk = tid >> 4;
            int sl = blk >> 3, hl = blk & 7;
            long src = ((long)(s0 + sl)) * (Nt / 8) * 64 + (long)(hA + hl) * 64 + (tid & 15) * 4;
            uint32_t dst = smem_addr(base + 4096 + blk * 64 + (tid & 15) * 4);
            cp16(dst, Bgh + src);
            cp16(dst + 4096, Bgl + src);   // BL at +1024 u32
        }
    };

    float acc[2][4][4] = {};
    int nT = Ksz / 32;

    loadStage(0, 0);
    asm volatile("cp.async.commit_group;" ::: "memory");

    for (int t = 0; t < nT; t++) {
        __syncthreads();
        if (t + 1 < nT) {
            loadStage(t + 1, (t + 1) & 1);
            asm volatile("cp.async.commit_group;" ::: "memory");
            asm volatile("cp.async.wait_group 1;" ::: "memory");
        } else {
            asm volatile("cp.async.wait_group 0;" ::: "memory");
        }
        __syncthreads();

        unsigned* base = sm + (t & 1) * STG_U32;

        #pragma unroll
        for (int kk = 0; kk < 2; kk++) {
            unsigned afh[2][4], afl[2][4], bfh[4][2], bfl[4][2];
            #pragma unroll
            for (int mi = 0; mi < 2; mi++) {
                int off = ((wm * 2 + mi) * 2 + kk) * 128 + lane * 4;
                uint4 v = *(uint4*)(base + off);
                afh[mi][0] = v.x; afh[mi][1] = v.y; afh[mi][2] = v.z; afh[mi][3] = v.w;
                v = *(uint4*)(base + 2048 + off);
                afl[mi][0] = v.x; afl[mi][1] = v.y; afl[mi][2] = v.z; afl[mi][3] = v.w;
            }
            #pragma unroll
            for (int ni = 0; ni < 4; ni++) {
                int off = 4096 + (kk * 8 + wn * 4 + ni) * 64 + lane * 2;
                uint2 v = *(uint2*)(base + off);
                bfh[ni][0] = v.x; bfh[ni][1] = v.y;
                v = *(uint2*)(base + 1024 + off);   // BL at +1024 u32
                bfl[ni][0] = v.x; bfl[ni][1] = v.y;
            }
            #pragma unroll
            for (int mi = 0; mi < 2; mi++)
                #pragma unroll
                for (int ni = 0; ni < 4; ni++) {
                    mma_bf16(acc[mi][ni], afl[mi], bfh[ni]);
                    mma_bf16(acc[mi][ni], afh[mi], bfl[ni]);
                    mma_bf16(acc[mi][ni], afh[mi], bfh[ni]);
                }
        }
    }

    // ---- epilogue ----
    float* Cb = C + (long)b * batchC;
    #pragma unroll
    for (int mi = 0; mi < 2; mi++) {
        #pragma unroll
        for (int ni = 0; ni < 4; ni++) {
            int r0 = rowBlk + wm * 32 + mi * 16 + gid;
            int c0 = colBlk + wn * 32 + ni * 8 + tig * 2;
            #pragma unroll
            for (int h = 0; h < 2; h++) {
                int r = r0 + h * 8;
                float v0 = acc[mi][ni][h * 2 + 0];
                float v1 = acc[mi][ni][h * 2 + 1];
                if (EPI == 1) {
                    float bias = sq[r];
                    float p0 = expf(v0 * PROJ_SCALE - bias) * RSQ_M;
                    float p1 = expf(v1 * PROJ_SCALE - bias) * RSQ_M;
                    unsigned hh, ll;
                    packpair(p0, p1, hh, ll);
                    long o = (long)r * (ldc / 2) + c0 / 2;
                    OH[o] = hh; OL[o] = ll;
                    if (OH2) {
                        int gg = (rowBlk >> 4) + wm * 2 + mi;
                        int ss = (colBlk >> 4) + wn * 2 + (ni >> 1);
                        long a = (((long)gg * SAout + ss) * 32 + gid * 4 + tig) * 4
                                 + (h + 2 * (ni & 1));
                        OH2[a] = hh; OL2[a] = ll;
                    }
                } else if (EPI == 2) {
                    long o = (long)r * ldc + c0;
                    atomicAdd(&Cb[o], v0);
                    atomicAdd(&Cb[o + 1], v1);
                } else {
                    float inv = 1.0f / den[b * Ln + r];
                    float fa0 = v0 * inv, fa1 = v1 * inv;
                    long go = (long)b * batchC + (long)r * ldc + c0;
                    C[go]     = content[go] + fa0;
                    C[go + 1] = content[go + 1] + fa1;
                    out2[go]     = fa0;
                    out2[go + 1] = fa1;
                }
            }
        }
    }
}

// ---------------------------------------------------------------------------
__global__ void z_kernel(const unsigned* __restrict__ ph, const unsigned* __restrict__ pl,
                         float* __restrict__ Z)
{
    int b = blockIdx.x, chunk = blockIdx.y;
    int cp = threadIdx.x & 127, half = threadIdx.x >> 7;
    const unsigned* rh = ph + ((long)b * KLn + chunk * 256 + half * 128) * (Mf/2) + cp;
    const unsigned* rl = pl + ((long)b * KLn + chunk * 256 + half * 128) * (Mf/2) + cp;
    float s0 = 0.f, s1 = 0.f;
    #pragma unroll 4
    for (int k = 0; k < 128; k++) {
        unsigned h = rh[(long)k * 128], l = rl[(long)k * 128];
        s0 += bfu((unsigned short)(h & 0xffff)) + bfu((unsigned short)(l & 0xffff));
        s1 += bfu((unsigned short)(h >> 16))    + bfu((unsigned short)(l >> 16));
    }
    atomicAdd(&Z[b * Mf + cp * 2],     s0);
    atomicAdd(&Z[b * Mf + cp * 2 + 1], s1);
}

__global__ void den_kernel(const unsigned* __restrict__ ph, const unsigned* __restrict__ pl,
                           const float* __restrict__ Z, float* __restrict__ den)
{
    int row  = blockIdx.x * 8 + (threadIdx.x >> 5);
    int lane = threadIdx.x & 31;
    int b = row / Ln;
    uint4 h = ((const uint4*)(ph + (long)row * (Mf/2)))[lane];
    uint4 l = ((const uint4*)(pl + (long)row * (Mf/2)))[lane];
    const float* z = Z + b * Mf + lane * 8;
    unsigned hw[4] = {h.x, h.y, h.z, h.w};
    unsigned lw[4] = {l.x, l.y, l.z, l.w};
    float s = 0.f;
    #pragma unroll
    for (int j = 0; j < 4; j++) {
        s += (bfu((unsigned short)(hw[j] & 0xffff)) + bfu((unsigned short)(lw[j] & 0xffff))) * z[2*j];
        s += (bfu((unsigned short)(hw[j] >> 16))    + bfu((unsigned short)(lw[j] >> 16)))    * z[2*j+1];
    }
    #pragma unroll
    for (int o = 16; o; o >>= 1) s += __shfl_xor_sync(0xffffffffu, s, o);
    if (lane == 0) den[row] = s + 1e-8f;
}

// ---------------------------------------------------------------------------
#define SPLIT_S 4

extern "C" void kernel_launch(void* const* d_in, const int* in_sizes, int n_in,
                              void* d_out, int out_size)
{
    const float* content = (const float*)d_in[0];
    const float* style   = (const float*)d_in[1];
    const float* W       = (const float*)d_in[2];
    float* out = (float*)d_out;

    unsigned *cAh,*cAl,*sAh,*sAl,*wBh,*wBl,*spBh,*spBl,*pqh,*pql,*pqch,*pqcl,
             *pkh,*pkl,*pkTh,*pkTl,*sBh,*sBl;
    float *S, *Z, *den, *sqq, *sqk;
    cudaGetSymbolAddress((void**)&cAh, g_cA_h);   cudaGetSymbolAddress((void**)&cAl, g_cA_l);
    cudaGetSymbolAddress((void**)&sAh, g_sA_h);   cudaGetSymbolAddress((void**)&sAl, g_sA_l);
    cudaGetSymbolAddress((void**)&wBh, g_wB_h);   cudaGetSymbolAddress((void**)&wBl, g_wB_l);
    cudaGetSymbolAddress((void**)&spBh, g_spB_h); cudaGetSymbolAddress((void**)&spBl, g_spB_l);
    cudaGetSymbolAddress((void**)&pqh, g_pq_h);   cudaGetSymbolAddress((void**)&pql, g_pq_l);
    cudaGetSymbolAddress((void**)&pqch, g_pqc_h); cudaGetSymbolAddress((void**)&pqcl, g_pqc_l);
    cudaGetSymbolAddress((void**)&pkh, g_pk_h);   cudaGetSymbolAddress((void**)&pkl, g_pk_l);
    cudaGetSymbolAddress((void**)&pkTh, g_pkT_h); cudaGetSymbolAddress((void**)&pkTl, g_pkT_l);
    cudaGetSymbolAddress((void**)&sBh, g_sB_h);   cudaGetSymbolAddress((void**)&sBl, g_sB_l);
    cudaGetSymbolAddress((void**)&S,   g_S);
    cudaGetSymbolAddress((void**)&Z,   g_Z);
    cudaGetSymbolAddress((void**)&den, g_den);
    cudaGetSymbolAddress((void**)&sqq, g_sq_q);
    cudaGetSymbolAddress((void**)&sqk, g_sq_k);

    // 1) sum-of-squares + canonical-A packs
    rowsumsq_pack<<<ROWS_Q / 16, 256>>>(content, sqq, cAh, cAl);
    rowsumsq_pack<<<ROWS_K / 16, 256>>>(style, sqk, sAh, sAl);

    // 2) canonical-B packs
    packB_canon<<<(32 * 32) / 8, 256>>>(W, wBh, wBl, Dn, Mf, 0, 0);
    packB_canon<<<(Bn * 512 * 64) / 8, 256>>>(style, spBh, spBl, KLn, Dn,
                                              (long)KLn * Dn, (long)512 * 64 * 32);

    // 3) zero S, Z
    zero_kernel<<<(Bn * Mf * Dn) / 256, 256>>>(S, Z);

    // 4) phi_q = phi(content @ W): std + canonical outputs
    tc_gemm<1><<<dim3(Mf/64, ROWS_Q/128, 1), 256>>>(
        cAh, cAl, wBh, wBl, nullptr, Dn, 32, Mf, Mf, 16,
        0, 0, 0, 1, sqq, pqh, pql, pqch, pqcl, nullptr, nullptr, nullptr);

    // 5) phi_k = phi(style @ W): std output only
    tc_gemm<1><<<dim3(Mf/64, ROWS_K/128, 1), 256>>>(
        sAh, sAl, wBh, wBl, nullptr, Dn, 32, Mf, Mf, 0,
        0, 0, 0, 1, sqk, pkh, pkl, nullptr, nullptr, nullptr, nullptr, nullptr);

    // 6) Z = colsum(phi_k)
    z_kernel<<<dim3(Bn, 32), 256>>>(pkh, pkl, Z);

    // 7) transpose-pack phi_k -> canonical A (SA=512 per batch)
    transpack<<<dim3(KLn/64, Mf/64, Bn), 256>>>(pkh, pkl, pkTh, pkTl);

    // 8) S[b][m][d] = sum_kl phi_k^T * style  (split-K atomics)
    tc_gemm<2><<<dim3(Dn/64, Mf/128, Bn * SPLIT_S), 256>>>(
        pkTh, pkTl, spBh, spBl, S, KLn/SPLIT_S, 512, Dn, Dn, 0,
        16L*512*128, (long)512*64*64, (long)Mf*Dn, SPLIT_S,
        nullptr, nullptr, nullptr, nullptr, nullptr, nullptr, nullptr, nullptr);

    // 9) canonical-B pack of S
    packB_canon<<<(Bn * 16 * 64) / 8, 256>>>(S, sBh, sBl, Mf, Dn,
                                             (long)Mf * Dn, (long)16 * 64 * 32);

    // 10) den
    den_kernel<<<ROWS_Q / 8, 256>>>(pqh, pql, Z, den);

    // 11) num GEMM fused final
    tc_gemm<3><<<dim3(Dn/64, Ln/128, Bn), 256>>>(
        pqch, pqcl, sBh, sBl, out, Mf, 16, Dn, Dn, 0,
        (long)(Ln/16)*16*128, (long)16*64*64, (long)Ln*Dn, 1,
        nullptr, nullptr, nullptr, nullptr, nullptr, den, content,
        out + (long)ROWS_Q * Dn);
}